// round 17
// baseline (speedup 1.0000x reference)
#include <cuda_runtime.h>
#include <cuda_fp16.h>
#include <cstdint>

#define HH 256
#define H2 512
#define GG 64
#define NNODE 20000
#define NEDGE 320000
#define NT1 256                   // gemm1: 8 warps, 2m x 4n
#define NT2 128                   // gemm2: 4 warps, 1m(32) x 4n

#define WP 264
#define AP 264
#define HP 520
#define A_WS_BYTES (256 * WP * 2)
#define A_AS_BYTES (64 * AP * 2)
#define A_SMEM (A_WS_BYTES + 2 * A_AS_BYTES)
#define TM2 32
#define B_WS_BYTES (128 * HP * 2)
#define B_HS_BYTES (TM2 * HP * 2)
#define B_SMEM (B_WS_BYTES + 2 * B_HS_BYTES)

#define NODE_RB 320000L
#define GLOB_RB 340032L
#define TOT_ROWS 340096L

__device__ __align__(16) __half g_w[3 * 262144];
__device__ __align__(16) float  g_gf[GG * HH];
__device__ __align__(16) __half g_a[TOT_ROWS * HH];
__device__ __align__(16) __half g_h[TOT_ROWS * H2];

// ---------- helpers ----------
__device__ __forceinline__ float gelu_fast(float x) {
    float u = x * (0.7978845608028654f + 0.035677408136300125f * x * x);
    float t;
    asm("tanh.approx.f32 %0, %1;" : "=f"(t) : "f"(u));
    return 0.5f * x * (1.0f + t);
}
__device__ __forceinline__ void hmma(float* c, const unsigned* a, unsigned b0, unsigned b1) {
    asm volatile(
        "mma.sync.aligned.m16n8k16.row.col.f32.f16.f16.f32 "
        "{%0,%1,%2,%3}, {%4,%5,%6,%7}, {%8,%9}, {%0,%1,%2,%3};\n"
        : "+f"(c[0]), "+f"(c[1]), "+f"(c[2]), "+f"(c[3])
        : "r"(a[0]), "r"(a[1]), "r"(a[2]), "r"(a[3]), "r"(b0), "r"(b1));
}
__device__ __forceinline__ void hmma16(unsigned* c, const unsigned* a, unsigned b0, unsigned b1) {
    asm volatile(
        "mma.sync.aligned.m16n8k16.row.col.f16.f16.f16.f16 "
        "{%0,%1}, {%2,%3,%4,%5}, {%6,%7}, {%0,%1};\n"
        : "+r"(c[0]), "+r"(c[1])
        : "r"(a[0]), "r"(a[1]), "r"(a[2]), "r"(a[3]), "r"(b0), "r"(b1));
}
__device__ __forceinline__ void ldm4(unsigned r[4], unsigned a) {
    asm volatile("ldmatrix.sync.aligned.m8n8.x4.shared.b16 {%0,%1,%2,%3}, [%4];"
                 : "=r"(r[0]), "=r"(r[1]), "=r"(r[2]), "=r"(r[3]) : "r"(a));
}
#define CP_COMMIT asm volatile("cp.async.commit_group;\n")
#define CP_WAIT1  asm volatile("cp.async.wait_group 1;\n")
#define CP_WAIT0  asm volatile("cp.async.wait_group 0;\n")
__device__ __forceinline__ void cpa(unsigned dst, const void* src) {
    asm volatile("cp.async.cg.shared.global [%0], [%1], 16;\n" ::"r"(dst), "l"(src));
}

// ---------- prep: fp16 + transpose weights to k-major ----------
__global__ void prep_kernel(const float* __restrict__ n1, const float* __restrict__ n2,
                            const float* __restrict__ g1, const float* __restrict__ g2,
                            const float* __restrict__ e1, const float* __restrict__ e2) {
    int idx = blockIdx.x * blockDim.x + threadIdx.x;
    int rid = idx >> 18;
    int r = idx & 262143;
    const float* w1 = (rid == 0) ? n1 : (rid == 1) ? g1 : e1;
    const float* w2 = (rid == 0) ? n2 : (rid == 1) ? g2 : e2;
    float v;
    if (r < 131072) { int n = r >> 8, k = r & 255; v = w1[(size_t)k * H2 + n]; }
    else { int q = r - 131072; int n = q >> 9, k = q & 511; v = w2[(size_t)k * HH + n]; }
    g_w[idx] = __float2half_rn(v);
}

// ---------- segment mean (node_batch sorted) ----------
__global__ void seg_mean_kernel(const float* __restrict__ nf, const int* __restrict__ batch, int n) {
    int gid = blockIdx.x;
    int lo, hi;
    { int a = 0, b = n;  while (a < b) { int m = (a + b) >> 1; if (batch[m] <  gid) a = m + 1; else b = m; } lo = a; }
    { int a = lo, b = n; while (a < b) { int m = (a + b) >> 1; if (batch[m] <= gid) a = m + 1; else b = m; } hi = a; }
    int col = threadIdx.x;
    float s = 0.f;
    for (int r = lo; r < hi; ++r) s += nf[(size_t)r * HH + col];
    g_gf[gid * HH + col] = s / fmaxf((float)(hi - lo), 1.0f);
}

// ---------- LN pass: rows [r0, ...) -> g_a fp16 at base rb; 2 rows per warp ----------
__global__ void ln_kernel(const float* __restrict__ Xp, long R, long r0, long rb,
                          const float* __restrict__ gamma, const float* __restrict__ beta,
                          int use_gf) {
    const float* X = use_gf ? g_gf : Xp;
    int warp = threadIdx.x >> 5, lane = threadIdx.x & 31;
    long row0 = r0 + (long)blockIdx.x * 16 + warp * 2;
    float4 gm0 = *(const float4*)(gamma + lane * 8);
    float4 gm1 = *(const float4*)(gamma + lane * 8 + 4);
    float4 bt0 = *(const float4*)(beta + lane * 8);
    float4 bt1 = *(const float4*)(beta + lane * 8 + 4);

    float4 v0[2], v1[2];
#pragma unroll
    for (int rr = 0; rr < 2; ++rr) {
        long row = row0 + rr;
        if (row < R) {
            v0[rr] = *(const float4*)(X + row * HH + lane * 8);
            v1[rr] = *(const float4*)(X + row * HH + lane * 8 + 4);
        } else {
            v0[rr] = make_float4(0.f, 0.f, 0.f, 0.f);
            v1[rr] = v0[rr];
        }
    }
    float s[2], q[2];
#pragma unroll
    for (int rr = 0; rr < 2; ++rr) {
        s[rr] = v0[rr].x + v0[rr].y + v0[rr].z + v0[rr].w + v1[rr].x + v1[rr].y + v1[rr].z + v1[rr].w;
        q[rr] = v0[rr].x * v0[rr].x + v0[rr].y * v0[rr].y + v0[rr].z * v0[rr].z + v0[rr].w * v0[rr].w
              + v1[rr].x * v1[rr].x + v1[rr].y * v1[rr].y + v1[rr].z * v1[rr].z + v1[rr].w * v1[rr].w;
    }
#pragma unroll
    for (int o = 16; o; o >>= 1) {
        s[0] += __shfl_xor_sync(0xFFFFFFFFu, s[0], o);
        s[1] += __shfl_xor_sync(0xFFFFFFFFu, s[1], o);
        q[0] += __shfl_xor_sync(0xFFFFFFFFu, q[0], o);
        q[1] += __shfl_xor_sync(0xFFFFFFFFu, q[1], o);
    }
#pragma unroll
    for (int rr = 0; rr < 2; ++rr) {
        long row = row0 + rr;
        if (row >= R) continue;
        float mean = s[rr] * (1.0f / HH);
        float rstd = rsqrtf(q[rr] * (1.0f / HH) - mean * mean + 1e-5f);
        __half2 p0 = __floats2half2_rn((v0[rr].x - mean) * rstd * gm0.x + bt0.x,
                                       (v0[rr].y - mean) * rstd * gm0.y + bt0.y);
        __half2 p1 = __floats2half2_rn((v0[rr].z - mean) * rstd * gm0.z + bt0.z,
                                       (v0[rr].w - mean) * rstd * gm0.w + bt0.w);
        __half2 p2 = __floats2half2_rn((v1[rr].x - mean) * rstd * gm1.x + bt1.x,
                                       (v1[rr].y - mean) * rstd * gm1.y + bt1.y);
        __half2 p3 = __floats2half2_rn((v1[rr].z - mean) * rstd * gm1.z + bt1.z,
                                       (v1[rr].w - mean) * rstd * gm1.w + bt1.w);
        uint4 u;
        u.x = *(unsigned*)&p0; u.y = *(unsigned*)&p1; u.z = *(unsigned*)&p2; u.w = *(unsigned*)&p3;
        *(uint4*)(g_a + (rb + row) * HH + lane * 8) = u;
    }
}

// ---------- pass A: H = gelu(A @ w1half + b1) -> g_h, tiles [t0, tend) ----------
__global__ void __launch_bounds__(NT1, 1)
gemm1_kernel(long R, long rb, long t0, long tend, int wbase, const float* __restrict__ bias1) {
    extern __shared__ char smem[];
    __half* As0 = (__half*)(smem + A_WS_BYTES);
    int h = blockIdx.x, tid = threadIdx.x;
    int warp = tid >> 5, lane = tid & 31, g = lane >> 2, tig = lane & 3;
    int wm = warp >> 2, wn = warp & 3, m0 = wm * 32;
    unsigned ws_s = (unsigned)__cvta_generic_to_shared(smem);
    unsigned as_s = (unsigned)__cvta_generic_to_shared(As0);
    const __half* Asrc = g_a + rb * HH;
    __half* Hdst = g_h + rb * H2;

    {
        const __half* src = g_w + wbase + (size_t)h * 256 * 256;
#pragma unroll
        for (int it = 0; it < 32; ++it) {
            int idx = tid + it * NT1;
            int row = idx >> 5, seg = idx & 31;
            cpa(ws_s + row * (WP * 2) + seg * 16, src + row * 256 + seg * 8);
        }
        CP_COMMIT;
    }
    int a_row = m0 + ((lane >> 3) & 1) * 8 + (lane & 7);
    int a_col = (lane >> 4) * 8;
    unsigned aoff0 = (unsigned)((a_row * AP + a_col) * 2);
    unsigned aoff1 = aoff0 + 16 * AP * 2;
    int b_n = wn * 64 + (lane >> 4) * 8 + (lane & 7);
    int b_col = ((lane >> 3) & 1) * 8;
    unsigned bbase = ws_s + (unsigned)((b_n * WP + b_col) * 2);

    long t = t0 + blockIdx.y;
    if (t < tend) {
#pragma unroll
        for (int it = 0; it < 8; ++it) {
            int idx = tid + it * NT1;
            int row = idx >> 5, seg = idx & 31;
            cpa(as_s + row * (AP * 2) + seg * 16, Asrc + ((size_t)t * 64 + row) * HH + seg * 8);
        }
        CP_COMMIT;
    }
    int buf = 0;
    for (; t < tend; t += gridDim.y, buf ^= 1) {
        long tn = t + gridDim.y;
        if (tn < tend) {
            unsigned db = as_s + (buf ^ 1) * A_AS_BYTES;
#pragma unroll
            for (int it = 0; it < 8; ++it) {
                int idx = tid + it * NT1;
                int row = idx >> 5, seg = idx & 31;
                cpa(db + row * (AP * 2) + seg * 16, Asrc + ((size_t)tn * 64 + row) * HH + seg * 8);
            }
            CP_COMMIT; CP_WAIT1;
        } else { CP_WAIT0; }
        __syncthreads();

        unsigned abuf = as_s + buf * A_AS_BYTES;
        float acc[2][8][4];
#pragma unroll
        for (int mt = 0; mt < 2; ++mt)
#pragma unroll
            for (int nt = 0; nt < 8; ++nt)
#pragma unroll
                for (int i = 0; i < 4; ++i) acc[mt][nt][i] = 0.f;
#pragma unroll 4
        for (int kt = 0; kt < 16; ++kt) {
            unsigned koff = (unsigned)kt * 32;
            unsigned am0[4], am1[4];
            ldm4(am0, abuf + aoff0 + koff);
            ldm4(am1, abuf + aoff1 + koff);
#pragma unroll
            for (int gi = 0; gi < 4; ++gi) {
                unsigned b[4];
                ldm4(b, bbase + gi * (16 * WP * 2) + koff);
                hmma(acc[0][2 * gi],     am0, b[0], b[1]);
                hmma(acc[0][2 * gi + 1], am0, b[2], b[3]);
                hmma(acc[1][2 * gi],     am1, b[0], b[1]);
                hmma(acc[1][2 * gi + 1], am1, b[2], b[3]);
            }
        }
        __syncthreads();
        __half* Hst = As0 + buf * (A_AS_BYTES / 2);
#pragma unroll
        for (int nt = 0; nt < 8; ++nt) {
            int col = wn * 64 + nt * 8 + 2 * tig;
            float2 bb = *(const float2*)(bias1 + h * 256 + col);
#pragma unroll
            for (int mt = 0; mt < 2; ++mt) {
                int r = m0 + mt * 16 + g;
                *(__half2*)(Hst + r * AP + col) =
                    __floats2half2_rn(gelu_fast(acc[mt][nt][0] + bb.x),
                                      gelu_fast(acc[mt][nt][1] + bb.y));
                *(__half2*)(Hst + (r + 8) * AP + col) =
                    __floats2half2_rn(gelu_fast(acc[mt][nt][2] + bb.x),
                                      gelu_fast(acc[mt][nt][3] + bb.y));
            }
        }
        __syncthreads();
        long base = t * 64;
#pragma unroll
        for (int it = 0; it < 8; ++it) {
            int idx = tid + it * NT1;
            int row = idx >> 5, seg = idx & 31;
            if (base + row < R) {
                uint4 u = *(const uint4*)(Hst + row * AP + seg * 8);
                *(uint4*)(Hdst + (base + row) * H2 + h * 256 + seg * 8) = u;
            }
        }
        __syncthreads();
    }
}

// ---------- pass B: out = H @ w2half + b2 + X (f16 accum), tiles [t0, tend) ----------
__global__ void __launch_bounds__(NT2, 1)
gemm2_kernel(const float* __restrict__ Xp, long R, long rb, long t0, long tend, int wbase,
             const float* __restrict__ bias2, float* __restrict__ out, int use_gf) {
    extern __shared__ char smem[];
    const float* X = use_gf ? g_gf : Xp;
    int h = blockIdx.x, tid = threadIdx.x;
    int warp = tid >> 5, lane = tid & 31, g = lane >> 2, tig = lane & 3;
    int wn = warp;
    unsigned ws_s = (unsigned)__cvta_generic_to_shared(smem);
    unsigned hs_s = ws_s + B_WS_BYTES;
    const __half* Hsrc = g_h + rb * H2;

    {
        const __half* src = g_w + wbase + 131072 + (size_t)h * 128 * 512;
#pragma unroll
        for (int it = 0; it < 64; ++it) {
            int idx = tid + it * NT2;
            int row = idx >> 6, seg = idx & 63;
            cpa(ws_s + row * (HP * 2) + seg * 16, src + row * 512 + seg * 8);
        }
        CP_COMMIT;
    }
    int a_row = ((lane >> 3) & 1) * 8 + (lane & 7);
    int a_col = (lane >> 4) * 8;
    unsigned aoff = (unsigned)((a_row * HP + a_col) * 2);
    int b_n = wn * 32 + (lane >> 4) * 8 + (lane & 7);
    int b_col = ((lane >> 3) & 1) * 8;
    unsigned bbase = ws_s + (unsigned)((b_n * HP + b_col) * 2);

    long t = t0 + blockIdx.y;
    if (t < tend) {
#pragma unroll
        for (int it = 0; it < 16; ++it) {
            int idx = tid + it * NT2;
            int row = idx >> 6, seg = idx & 63;
            cpa(hs_s + row * (HP * 2) + seg * 16, Hsrc + ((size_t)t * TM2 + row) * H2 + seg * 8);
        }
        CP_COMMIT;
    }
    int buf = 0;
    for (; t < tend; t += gridDim.y, buf ^= 1) {
        long tn = t + gridDim.y;
        if (tn < tend) {
            unsigned db = hs_s + (buf ^ 1) * B_HS_BYTES;
#pragma unroll
            for (int it = 0; it < 16; ++it) {
                int idx = tid + it * NT2;
                int row = idx >> 6, seg = idx & 63;
                cpa(db + row * (HP * 2) + seg * 16, Hsrc + ((size_t)tn * TM2 + row) * H2 + seg * 8);
            }
            CP_COMMIT; CP_WAIT1;
        } else { CP_WAIT0; }
        __syncthreads();

        unsigned hbuf = hs_s + buf * B_HS_BYTES;
        float accf[2][4][4];
        unsigned acc16[2][4][2];
#pragma unroll
        for (int mi = 0; mi < 2; ++mi)
#pragma unroll
            for (int nf = 0; nf < 4; ++nf) {
                acc16[mi][nf][0] = 0u; acc16[mi][nf][1] = 0u;
#pragma unroll
                for (int i = 0; i < 4; ++i) accf[mi][nf][i] = 0.f;
            }
#pragma unroll 8
        for (int kt = 0; kt < 32; ++kt) {
            unsigned koff = (unsigned)kt * 32;
            unsigned a[2][4], b[2][4];
            ldm4(a[0], hbuf + aoff + koff);
            ldm4(a[1], hbuf + aoff + 16 * HP * 2 + koff);
            ldm4(b[0], bbase + koff);
            ldm4(b[1], bbase + 16 * HP * 2 + koff);
#pragma unroll
            for (int mi = 0; mi < 2; ++mi)
#pragma unroll
                for (int ni = 0; ni < 2; ++ni) {
                    hmma16(acc16[mi][2 * ni],     a[mi], b[ni][0], b[ni][1]);
                    hmma16(acc16[mi][2 * ni + 1], a[mi], b[ni][2], b[ni][3]);
                }
            if ((kt & 7) == 7) {
#pragma unroll
                for (int mi = 0; mi < 2; ++mi)
#pragma unroll
                    for (int nf = 0; nf < 4; ++nf) {
                        float2 lo = __half22float2(*(__half2*)&acc16[mi][nf][0]);
                        float2 hi = __half22float2(*(__half2*)&acc16[mi][nf][1]);
                        accf[mi][nf][0] += lo.x; accf[mi][nf][1] += lo.y;
                        accf[mi][nf][2] += hi.x; accf[mi][nf][3] += hi.y;
                        acc16[mi][nf][0] = 0u; acc16[mi][nf][1] = 0u;
                    }
            }
        }
        long base = t * TM2;
#pragma unroll
        for (int mi = 0; mi < 2; ++mi) {
#pragma unroll
            for (int nf = 0; nf < 4; ++nf) {
                int col = h * 128 + wn * 32 + nf * 8 + 2 * tig;
                float2 bb = *(const float2*)(bias2 + col);
                int r = mi * 16 + g;
                long gr0 = base + r, gr1 = gr0 + 8;
                if (gr0 < R) {
                    float2 x = *(const float2*)(X + gr0 * HH + col);
                    *(float2*)(out + gr0 * HH + col) =
                        make_float2(accf[mi][nf][0] + bb.x + x.x, accf[mi][nf][1] + bb.y + x.y);
                }
                if (gr1 < R) {
                    float2 x = *(const float2*)(X + gr1 * HH + col);
                    *(float2*)(out + gr1 * HH + col) =
                        make_float2(accf[mi][nf][2] + bb.x + x.x, accf[mi][nf][3] + bb.y + x.y);
                }
            }
        }
        __syncthreads();
    }
}

// ---------- persistent stream/event handles (created once; see R16 post-mortem) ----------
static cudaStream_t g_sL = nullptr, g_sE = nullptr, g_sF = nullptr;
static cudaEvent_t  g_e0, g_eP, g_eL[4], g_eG[4], g_eJ1, g_eJ2, g_eJ3;

// ---------- launch ----------
extern "C" void kernel_launch(void* const* d_in, const int* in_sizes, int n_in,
                              void* d_out, int out_size) {
    const float* nodef = (const float*)d_in[0];
    const float* edgef = (const float*)d_in[1];
    const int*   batch = (const int*)d_in[2];
    int pb = n_in - 18;
    const float* P[18];
    for (int i = 0; i < 18; ++i) P[i] = (const float*)d_in[pb + i];

    float* out   = (float*)d_out;
    float* out_g = out;
    float* out_n = out + (size_t)GG * HH;
    float* out_e = out_n + (size_t)NNODE * HH;

    if (g_sL == nullptr) {
        cudaStreamCreateWithFlags(&g_sL, cudaStreamNonBlocking);
        cudaStreamCreateWithFlags(&g_sE, cudaStreamNonBlocking);
        cudaStreamCreateWithFlags(&g_sF, cudaStreamNonBlocking);
        cudaEventCreateWithFlags(&g_e0, cudaEventDisableTiming);
        cudaEventCreateWithFlags(&g_eP, cudaEventDisableTiming);
        for (int k = 0; k < 4; ++k) {
            cudaEventCreateWithFlags(&g_eL[k], cudaEventDisableTiming);
            cudaEventCreateWithFlags(&g_eG[k], cudaEventDisableTiming);
        }
        cudaEventCreateWithFlags(&g_eJ1, cudaEventDisableTiming);
        cudaEventCreateWithFlags(&g_eJ2, cudaEventDisableTiming);
        cudaEventCreateWithFlags(&g_eJ3, cudaEventDisableTiming);
        cudaFuncSetAttribute(gemm1_kernel, cudaFuncAttributeMaxDynamicSharedMemorySize, A_SMEM);
        cudaFuncSetAttribute(gemm2_kernel, cudaFuncAttributeMaxDynamicSharedMemorySize, B_SMEM);
    }

    // fork
    cudaEventRecord(g_e0, 0);
    cudaStreamWaitEvent(g_sL, g_e0, 0);
    cudaStreamWaitEvent(g_sE, g_e0, 0);
    cudaStreamWaitEvent(g_sF, g_e0, 0);

    // default: prep first (edge GEMMs need weights)
    prep_kernel<<<3072, 256>>>(P[2], P[4], P[8], P[10], P[14], P[16]);
    cudaEventRecord(g_eP, 0);

    // sL: edge LN in 4 chunks of 80000 rows
    for (int k = 0; k < 4; ++k) {
        ln_kernel<<<5000, 256, 0, g_sL>>>(edgef, NEDGE, (long)k * 80000, 0L, P[12], P[13], 0);
        cudaEventRecord(g_eL[k], g_sL);
    }

    // default: node + global pipeline
    ln_kernel<<<1250, 256>>>(nodef, NNODE, 0L, NODE_RB, P[0], P[1], 0);
    seg_mean_kernel<<<GG, HH>>>(nodef, batch, NNODE);
    ln_kernel<<<4, 256>>>(nullptr, GG, 0L, GLOB_RB, P[6], P[7], 1);
    gemm1_kernel<<<dim3(2, 74), NT1, A_SMEM>>>(NNODE, NODE_RB, 0L, 313L, 0, P[3]);
    gemm2_kernel<<<dim3(2, 74), NT2, B_SMEM>>>(nodef, NNODE, NODE_RB, 0L, 625L, 0, P[5], out_n, 0);
    gemm1_kernel<<<dim3(2, 1), NT1, A_SMEM>>>(GG, GLOB_RB, 0L, 1L, 262144, P[9]);
    gemm2_kernel<<<dim3(2, 2), NT2, B_SMEM>>>(nullptr, GG, GLOB_RB, 0L, 2L, 262144, P[11], out_g, 1);

    // sE: edge gemm1 in 4 chunks (each gated on its LN chunk)
    cudaStreamWaitEvent(g_sE, g_eP, 0);
    for (int k = 0; k < 4; ++k) {
        cudaStreamWaitEvent(g_sE, g_eL[k], 0);
        gemm1_kernel<<<dim3(2, 74), NT1, A_SMEM, g_sE>>>(
            NEDGE, 0L, (long)k * 1250, (long)(k + 1) * 1250, 524288, P[15]);
        cudaEventRecord(g_eG[k], g_sE);
    }

    // sF: edge gemm2 in 4 chunks, each gated on the matching gemm1 chunk — co-runs with gemm1(k+1)
    cudaStreamWaitEvent(g_sF, g_eP, 0);
    for (int k = 0; k < 4; ++k) {
        cudaStreamWaitEvent(g_sF, g_eG[k], 0);
        gemm2_kernel<<<dim3(2, 74), NT2, B_SMEM, g_sF>>>(
            edgef, NEDGE, 0L, (long)k * 2500, (long)(k + 1) * 2500, 524288, P[17], out_e, 0);
    }

    // join
    cudaEventRecord(g_eJ1, g_sE);
    cudaStreamWaitEvent(0, g_eJ1, 0);
    cudaEventRecord(g_eJ2, g_sL);
    cudaStreamWaitEvent(0, g_eJ2, 0);
    cudaEventRecord(g_eJ3, g_sF);
    cudaStreamWaitEvent(0, g_eJ3, 0);
}